// round 9
// baseline (speedup 1.0000x reference)
#include <cuda_runtime.h>
#include <cstdint>

// Problem constants
#define BB   64
#define TT   2048
#define II   200
#define HH   100
#define G4   400   // 4*H
#define NPROJ 84   // producer CTAs (blockIdx 0..83)
#define NSCAN 64   // consumer CTAs (blockIdx 84..147)
#define NCTA  (NPROJ + NSCAN)

// Scratch: xg[t][b][j] (t-major), ~210MB. Produced by proj role, consumed by scan.
__device__ float g_xg[(size_t)TT * BB * G4];
// Per-timestep ready counters (4 column-tiles each). Reset every launch.
__device__ int g_ready[TT];

// ---- packed fp32x2 helpers ---------------------------------------------
union f2u { float2 f; unsigned long long u; };
union f4u { float4 f; ulonglong2 u; };

__device__ __forceinline__ unsigned long long ffma2(unsigned long long a,
                                                    unsigned long long b,
                                                    unsigned long long c) {
    unsigned long long d;
    asm("fma.rn.f32x2 %0, %1, %2, %3;" : "=l"(d) : "l"(a), "l"(b), "l"(c));
    return d;
}
__device__ __forceinline__ unsigned long long fadd2(unsigned long long a,
                                                    unsigned long long b) {
    unsigned long long d;
    asm("add.rn.f32x2 %0, %1, %2;" : "=l"(d) : "l"(a), "l"(b));
    return d;
}
__device__ __forceinline__ float tanh_(float x) {
    return __fdividef(2.0f, 1.0f + __expf(-2.0f * x)) - 1.0f;
}
__device__ __forceinline__ int ld_acq(const int* p) {
    int v;
    asm volatile("ld.acquire.gpu.global.b32 %0, [%1];" : "=r"(v) : "l"(p));
    return v;
}

// ---- shared memory union ------------------------------------------------
#define KC 40
#define ASTR 68          // padded A stride (floats), 272B (16B aligned)
struct SmemProj { float As[KC * ASTR]; float Bs[KC * HH]; };   // 26.9 KB
struct SmemScan { float h[2][HH]; };
union SmemU { SmemProj p; SmemScan s; };

// ---- flag reset (runs before fused kernel each launch) ------------------
__global__ void reset_kernel() {
    int i = blockIdx.x * 256 + threadIdx.x;
    if (i < TT) g_ready[i] = 0;
}

// ---- producer role: input projection ------------------------------------
// One tile = one timestep t x 100 cols x all 64 batches. 8192 tiles over 84
// CTAs, swept in ascending-t order. After a tile: fence + atomicAdd(ready[t]).
__device__ __forceinline__ void proj_role(SmemProj& sm,
                                          const float* __restrict__ x,
                                          const float* __restrict__ Wih,
                                          const float* __restrict__ bih,
                                          const float* __restrict__ bhh) {
    const int tid = threadIdx.x;
    const int tx  = tid % 25;        // cols tx*4 .. tx*4+3 (within 100)
    const int ty  = tid / 25;        // batches ty*4 .. ty*4+3
    const int cta = blockIdx.x;

    for (int tile = cta; tile < TT * 4; tile += NPROJ) {
        const int t  = tile >> 2;
        const int c0 = (tile & 3) * HH;

        unsigned long long acc[4][2];
        #pragma unroll
        for (int r = 0; r < 4; ++r) { acc[r][0] = 0ULL; acc[r][1] = 0ULL; }

        for (int ch = 0; ch < II / KC; ++ch) {
            const int k0 = ch * KC;
            __syncthreads();   // previous chunk / previous tile consumed

            // Stage A: x[b][t][k0..k0+39] for b=0..63, transposed to As[k][b]
            for (int idx = tid; idx < 64 * (KC / 4); idx += 400) {
                int r = idx / (KC / 4);
                int q = idx - r * (KC / 4);
                float4 v = *(const float4*)&x[((size_t)r * TT + t) * II + k0 + 4 * q];
                sm.As[(4 * q + 0) * ASTR + r] = v.x;
                sm.As[(4 * q + 1) * ASTR + r] = v.y;
                sm.As[(4 * q + 2) * ASTR + r] = v.z;
                sm.As[(4 * q + 3) * ASTR + r] = v.w;
            }
            // Stage B (transposing): thread t<100 owns W_ih row c0+t (L2-res.)
            if (tid < HH) {
                const float* wrow = &Wih[(size_t)(c0 + tid) * II + k0];
                #pragma unroll
                for (int q = 0; q < KC / 4; ++q) {
                    float4 v = *(const float4*)&wrow[4 * q];
                    sm.Bs[(4 * q + 0) * HH + tid] = v.x;
                    sm.Bs[(4 * q + 1) * HH + tid] = v.y;
                    sm.Bs[(4 * q + 2) * HH + tid] = v.z;
                    sm.Bs[(4 * q + 3) * HH + tid] = v.w;
                }
            }
            __syncthreads();

            #pragma unroll 4
            for (int k = 0; k < KC; ++k) {
                f4u a4, w4;
                a4.f = *(const float4*)&sm.As[k * ASTR + ty * 4];
                w4.f = *(const float4*)&sm.Bs[k * HH + tx * 4];
                float ar[4] = {a4.f.x, a4.f.y, a4.f.z, a4.f.w};
                #pragma unroll
                for (int r = 0; r < 4; ++r) {
                    f2u av; av.f.x = ar[r]; av.f.y = ar[r];
                    acc[r][0] = ffma2(av.u, w4.u.x, acc[r][0]);
                    acc[r][1] = ffma2(av.u, w4.u.y, acc[r][1]);
                }
            }
        }

        // Epilogue: bias + store to g_xg[t][b][col]
        const int col = c0 + tx * 4;
        float4 bi = *(const float4*)&bih[col];
        float4 bh = *(const float4*)&bhh[col];
        float4 bias = make_float4(bi.x + bh.x, bi.y + bh.y, bi.z + bh.z, bi.w + bh.w);
        #pragma unroll
        for (int r = 0; r < 4; ++r) {
            int b = ty * 4 + r;
            f2u p0, p1; p0.u = acc[r][0]; p1.u = acc[r][1];
            float4 o = make_float4(p0.f.x + bias.x, p0.f.y + bias.y,
                                   p1.f.x + bias.z, p1.f.y + bias.w);
            *(float4*)&g_xg[((size_t)t * BB + b) * G4 + col] = o;
        }

        __threadfence();     // each thread's stores visible at gpu scope
        __syncthreads();     // ... before tid0 publishes
        if (tid == 0) atomicAdd(&g_ready[t], 1);
    }
}

// ---- consumer role: sequential LSTM scan (R6 inner loop) ----------------
// One CTA per batch, 400 threads, quad layout (threads 4j..4j+3 = gates
// i,f,g,o of unit j). h double-buffered, ONE barrier/step, leader-only
// tail. xg prefetched 4 steps ahead. Ready-flags verified in 40-flag
// windows once per 32 steps (covers every load issued in the block).
#define FWIN 40

__device__ __forceinline__ void verify_flags(int W, int lane, int nl,
                                             unsigned wmask) {
    bool ok;
    do {
        ok = true;
        for (int k = lane; k < FWIN; k += nl) {
            int idx = W + k;
            idx = (idx < TT) ? idx : (TT - 1);
            ok &= (ld_acq(&g_ready[idx]) == 4);
        }
    } while (!__all_sync(wmask, ok));
}

__device__ __forceinline__ void scan_role(SmemScan& sm,
                                          const float* __restrict__ Whh,
                                          float* __restrict__ out) {
    const int b    = blockIdx.x - NPROJ;
    const int tid  = threadIdx.x;
    const int j    = tid >> 2;
    const int g    = tid & 3;
    const int lane = tid & 31;
    const unsigned qmask = 0xFu << (lane & ~3);
    const int nl = (tid < 384) ? 32 : 16;              // warp 12 is partial
    const unsigned wmask = (nl == 32) ? 0xffffffffu : 0xffffu;

    // W_hh row (g*100 + j) in registers: 25 float4
    f4u wreg[HH / 4];
    const float4* wr = (const float4*)(Whh + (size_t)(g * HH + j) * HH);
    #pragma unroll
    for (int q = 0; q < HH / 4; ++q) wreg[q].f = wr[q];

    float c = 0.0f, hval = 0.0f;
    if (tid < HH) sm.h[0][tid] = 0.0f;
    __syncthreads();

    const float* xg = g_xg + (size_t)b * G4 + (g * HH + j);
    const size_t ts = (size_t)BB * G4;

    verify_flags(0, lane, nl, wmask);      // flags 0..39 ready

    float cur[4], nxt[4];
    #pragma unroll
    for (int i = 0; i < 4; ++i) cur[i] = __ldcg(&xg[(size_t)i * ts]);

    int p = 0;
    for (int W = 0; W < TT; W += 32) {
        if (W) verify_flags(W, lane, nl, wmask);   // flags W..W+39 ready

        for (int tg = W; tg < W + 32; tg += 4) {
            // issue next group's loads (t <= tg+7 <= W+39: verified)
            #pragma unroll
            for (int i = 0; i < 4; ++i) {
                int t = tg + 4 + i; t = (t < TT) ? t : (TT - 1);
                nxt[i] = __ldcg(&xg[(size_t)t * ts]);
            }

            #pragma unroll
            for (int i = 0; i < 4; ++i) {
                unsigned long long a0 = 0ULL, a1 = 0ULL, a2 = 0ULL, a3 = 0ULL;
                const float4* hb = (const float4*)sm.h[p];
                #pragma unroll
                for (int q = 0; q < HH / 4; ++q) {
                    f4u h4; h4.f = hb[q];          // broadcast LDS.128
                    if (q & 1) {
                        a2 = ffma2(wreg[q].u.x, h4.u.x, a2);
                        a3 = ffma2(wreg[q].u.y, h4.u.y, a3);
                    } else {
                        a0 = ffma2(wreg[q].u.x, h4.u.x, a0);
                        a1 = ffma2(wreg[q].u.y, h4.u.y, a1);
                    }
                }
                f2u s0, s1;
                s0.u = fadd2(a0, a2);
                s1.u = fadd2(a1, a3);
                float gate = (s0.f.x + s0.f.y) + (s1.f.x + s1.f.y) + cur[i];

                // branch-free activation: g==2 -> tanh, else sigmoid
                bool is_t = (g == 2);
                float xx = is_t ? 2.0f * gate : gate;
                float sg = __fdividef(1.0f, 1.0f + __expf(-xx));
                float a  = is_t ? fmaf(2.0f, sg, -1.0f) : sg;

                // quad combine, leader-only tail (as in the 1483us kernel)
                float fg = __shfl_down_sync(qmask, a, 1, 4);
                float gg = __shfl_down_sync(qmask, a, 2, 4);
                float og = __shfl_down_sync(qmask, a, 3, 4);
                if (g == 0) {
                    c    = fg * c + a * gg;
                    hval = og * tanh_(c);
                    sm.h[p ^ 1][j] = hval;         // write OTHER buffer
                }
                __syncthreads();
                p ^= 1;
            }

            #pragma unroll
            for (int i = 0; i < 4; ++i) cur[i] = nxt[i];
        }
    }

    if (g == 0) out[b * HH + j] = hval;
}

// ---- fused persistent kernel --------------------------------------------
__global__ __launch_bounds__(400, 1)
void fused_kernel(const float* __restrict__ x,
                  const float* __restrict__ Wih,
                  const float* __restrict__ Whh,
                  const float* __restrict__ bih,
                  const float* __restrict__ bhh,
                  float* __restrict__ out) {
    __shared__ SmemU sm;
    if (blockIdx.x < NPROJ) {
        proj_role(sm.p, x, Wih, bih, bhh);
    } else {
        scan_role(sm.s, Whh, out);
    }
}

// ---- launch ------------------------------------------------------------
extern "C" void kernel_launch(void* const* d_in, const int* in_sizes, int n_in,
                              void* d_out, int out_size) {
    const float* x   = (const float*)d_in[0];   // [64,2048,200]
    const float* Wih = (const float*)d_in[1];   // [400,200]
    const float* Whh = (const float*)d_in[2];   // [400,100]
    const float* bih = (const float*)d_in[3];   // [400]
    const float* bhh = (const float*)d_in[4];   // [400]
    float* out = (float*)d_out;                 // [64,100]

    reset_kernel<<<(TT + 255) / 256, 256>>>();
    fused_kernel<<<NCTA, 400>>>(x, Wih, Whh, bih, bhh, out);
}